// round 1
// baseline (speedup 1.0000x reference)
#include <cuda_runtime.h>
#include <math.h>
#include <stdint.h>

#define NC    80
#define NB    16
#define NG    16
#define ATOT  33600
#define LV0   25600
#define LV1   6400
#define LV2   1600
#define TPB   256
#define NBLKX 132                 // ceil(33600/256)
#define NPART (NBLKX*NB)          // 2112

// ---------------- scratch (device globals; no allocations) ----------------
__device__ float        g_cost[NB*NG*ATOT];   // 34.4 MB
__device__ float        g_iou [NB*NG*ATOT];   // 34.4 MB  (iou masked by union)
__device__ unsigned int g_match[NB*ATOT];     // per-anchor GT match bitmask
__device__ double g_pc[NPART], g_pb[NPART], g_pl[NPART], g_pf[NPART];

// ---------------- helpers ----------------
__device__ __forceinline__ const float* resolve(const float* p0, const float* p1, const float* p2,
                                                int b, int a, int& hw, int& HW, int& W, float& s) {
    if (a < LV0)      { hw = a;             HW = LV0; W = 160; s = 8.f;  return p0 + (size_t)b*85*LV0; }
    if (a < LV0+LV1)  { hw = a - LV0;       HW = LV1; W = 80;  s = 16.f; return p1 + (size_t)b*85*LV1; }
    hw = a - (LV0+LV1); HW = LV2; W = 40; s = 32.f; return p2 + (size_t)b*85*LV2;
}

__device__ __forceinline__ unsigned int fenc(float f) {
    unsigned int u = __float_as_uint(f);
    return (u & 0x80000000u) ? ~u : (u | 0x80000000u);   // monotonic float->uint
}
__device__ __forceinline__ float fdec(unsigned int u) {
    return (u & 0x80000000u) ? __uint_as_float(u & 0x7FFFFFFFu) : __uint_as_float(~u);
}
// maintain sorted-ascending top-10 (k[0] = min)
__device__ __forceinline__ void ins10(unsigned long long* k, unsigned long long key) {
    if (key <= k[0]) return;
    k[0] = key;
    #pragma unroll
    for (int j = 0; j < 9; j++) {
        if (k[j] > k[j+1]) { unsigned long long t = k[j]; k[j] = k[j+1]; k[j+1] = t; }
        else break;
    }
}

// ---------------- kZ: zero match mask ----------------
__global__ void kZ() {
    int i = blockIdx.x*blockDim.x + threadIdx.x;
    if (i < NB*ATOT) g_match[i] = 0u;
}

// ---------------- kB: geometry + cost + iou ----------------
__global__ __launch_bounds__(TPB) void kB(const float* __restrict__ p0, const float* __restrict__ p1,
                                          const float* __restrict__ p2, const float* __restrict__ lab) {
    __shared__ float sl[NG*5];
    __shared__ int   stc[NG];
    int b = blockIdx.y, tid = threadIdx.x;
    if (tid < NG*5) sl[tid] = lab[b*NG*5 + tid];
    if (tid < NG)   stc[tid] = (int)lab[b*NG*5 + tid*5 + 4];
    __syncthreads();
    int a = blockIdx.x*TPB + tid;
    if (a >= ATOT) return;
    int hw, HW, W; float s;
    const float* P = resolve(p0,p1,p2,b,a,hw,HW,W,s);
    int gx = hw % W, gy = hw / W;
    float xc = ((float)gx + 0.5f)*s, yc = ((float)gy + 0.5f)*s;
    float rr = 2.5f*s;
    unsigned int inter = 0; bool uni = false;
    #pragma unroll
    for (int g = 0; g < NG; g++) {
        float bx = sl[g*5+0], by = sl[g*5+1], bw = sl[g*5+2], bh = sl[g*5+3];
        bool ib = (xc > bx - bw*0.5f) & (xc < bx + bw*0.5f) & (yc > by - bh*0.5f) & (yc < by + bh*0.5f);
        bool im = (xc > bx - rr) & (xc < bx + rr) & (yc > by - rr) & (yc < by + rr);
        inter |= ((unsigned)(ib & im)) << g;
        uni = uni | ib | im;
    }
    size_t rowbase = (size_t)b*NG*ATOT + a;
    if (!uni) {   // never enters any top-10 (>=75 union anchors/batch); sentinel only
        #pragma unroll
        for (int g = 0; g < NG; g++) {
            g_cost[rowbase + (size_t)g*ATOT] = 2e9f;
            g_iou [rowbase + (size_t)g*ATOT] = 0.f;
        }
        return;
    }
    float tx = P[hw], ty = P[HW+hw], tw = P[2*HW+hw], th = P[3*HW+hw], cf = P[4*HW+hw];
    float px = (tx + (float)gx)*s, py = (ty + (float)gy)*s;
    float pw = __expf(tw)*s, ph = __expf(th)*s;
    float dq = 1.f + __expf(-cf);
    const float* Pc = P + 5*HW + hw;
    // base = -sum_c log(1 - p_c),  p_c = rsqrt((1+e^-x)(1+e^-q)); grouped log of products
    float base = 0.f, prod = 1.f;
    for (int c = 0; c < NC; c++) {
        float x = Pc[c*HW];
        float d = 1.f + __expf(-x);
        prod *= (1.f - rsqrtf(d*dq));
        if ((c & 15) == 15) { base -= __logf(prod); prod = 1.f; }
    }
    float ax1 = px - pw*0.5f, ay1 = py - ph*0.5f, ax2 = px + pw*0.5f, ay2 = py + ph*0.5f;
    float pa = pw*ph;
    #pragma unroll
    for (int g = 0; g < NG; g++) {
        float bx = sl[g*5+0], by = sl[g*5+1], bw = sl[g*5+2], bh = sl[g*5+3];
        float x = Pc[stc[g]*HW];
        float d = 1.f + __expf(-x);
        float m = d*dq;
        float lp  = fmaxf(-0.5f*__logf(m), -100.f);              // log p at target class
        float l1m = fmaxf(__logf(1.f - rsqrtf(m)), -100.f);       // log(1-p) at target class
        float iw = fmaxf(fminf(bx + bw*0.5f, ax2) - fmaxf(bx - bw*0.5f, ax1), 0.f);
        float ih = fmaxf(fminf(by + bh*0.5f, ay2) - fmaxf(by - bh*0.5f, ay1), 0.f);
        float it = iw*ih;
        float iou = it / (bw*bh + pa - it + 1e-16f);
        float cst = base - lp + l1m - 3.f*__logf(iou + 1e-8f)
                  + (((inter >> g) & 1u) ? 0.f : 100000.f);
        g_cost[rowbase + (size_t)g*ATOT] = cst;
        g_iou [rowbase + (size_t)g*ATOT] = iou;
    }
}

// ---------------- kC: per-(b,g) top-k + scatter ----------------
__device__ void extract10(unsigned long long* cand, unsigned long long* red,
                          unsigned long long* selk, int tid) {
    for (int r = 0; r < 10; r++) {
        unsigned long long m = 0ull;
        #pragma unroll
        for (int j = 0; j < 10; j++) { unsigned long long v = cand[tid*10+j]; m = v > m ? v : m; }
        red[tid] = m; __syncthreads();
        for (int s2 = TPB/2; s2 > 0; s2 >>= 1) {
            if (tid < s2) { unsigned long long v = red[tid+s2]; if (v > red[tid]) red[tid] = v; }
            __syncthreads();
        }
        unsigned long long gm = red[0];
        if (tid == 0) selk[r] = gm;
        #pragma unroll
        for (int j = 0; j < 10; j++) if (cand[tid*10+j] == gm) cand[tid*10+j] = 0ull;
        __syncthreads();
    }
}

__global__ __launch_bounds__(TPB) void kC() {
    __shared__ unsigned long long cand[TPB*10];
    __shared__ unsigned long long red[TPB];
    __shared__ unsigned long long selk[10];
    __shared__ int sdynk;
    int row = blockIdx.x;
    int b = row >> 4, g = row & 15;
    const float* crow = g_cost + (size_t)row*ATOT;
    const float* irow = g_iou  + (size_t)row*ATOT;
    int tid = threadIdx.x;
    unsigned long long loc[10];

    // pass 1: iou_m top-10 (values) -> dyn_k
    #pragma unroll
    for (int j = 0; j < 10; j++) loc[j] = 0ull;
    for (int i = tid; i < ATOT; i += TPB) {
        unsigned long long key = ((unsigned long long)fenc(irow[i]) << 32)
                               | (unsigned long long)(0xFFFFFFFFu - (unsigned)i);
        ins10(loc, key);
    }
    #pragma unroll
    for (int j = 0; j < 10; j++) cand[tid*10+j] = loc[j];
    __syncthreads();
    extract10(cand, red, selk, tid);
    if (tid == 0) {
        float sum = 0.f;
        for (int k = 0; k < 10; k++) sum += fdec((unsigned int)(selk[k] >> 32));
        int dk = (int)sum;                    // truncation, matches astype(int32)
        sdynk = dk < 1 ? 1 : (dk > 10 ? 10 : dk);
    }
    __syncthreads();

    // pass 2: (-cost) top-10 (indices; tie -> lower index, matches jax top_k)
    #pragma unroll
    for (int j = 0; j < 10; j++) loc[j] = 0ull;
    for (int i = tid; i < ATOT; i += TPB) {
        unsigned long long key = ((unsigned long long)fenc(-crow[i]) << 32)
                               | (unsigned long long)(0xFFFFFFFFu - (unsigned)i);
        ins10(loc, key);
    }
    #pragma unroll
    for (int j = 0; j < 10; j++) cand[tid*10+j] = loc[j];
    __syncthreads();
    extract10(cand, red, selk, tid);
    if (tid == 0) {
        int dk = sdynk;
        for (int k = 0; k < dk; k++) {
            unsigned int ai = 0xFFFFFFFFu - (unsigned int)(selk[k] & 0xFFFFFFFFull);
            atomicOr(&g_match[b*ATOT + (int)ai], 1u << g);
        }
    }
}

// ---------------- kD: finalize + loss partials ----------------
__global__ __launch_bounds__(TPB) void kD(const float* __restrict__ p0, const float* __restrict__ p1,
                                          const float* __restrict__ p2, const float* __restrict__ lab) {
    __shared__ float sl[NG*5];
    __shared__ int   stc[NG];
    __shared__ double sred[TPB];
    int b = blockIdx.y, tid = threadIdx.x;
    if (tid < NG*5) sl[tid] = lab[b*NG*5 + tid];
    if (tid < NG)   stc[tid] = (int)lab[b*NG*5 + tid*5 + 4];
    __syncthreads();
    int a = blockIdx.x*TPB + tid;
    double aC = 0.0, aB = 0.0, aL = 0.0, aF = 0.0;
    if (a < ATOT) {
        int hw, HW, W; float s;
        const float* P = resolve(p0,p1,p2,b,a,hw,HW,W,s);
        float cf = P[4*HW+hw];
        aC = (double)(fmaxf(cf, 0.f) + log1pf(expf(-fabsf(cf))));   // bce(conf, 0)
        unsigned int mask = g_match[b*ATOT + a];
        if (mask) {
            int gs;
            if (__popc(mask) > 1) {            // conflict -> argmin over g (first min)
                size_t cb = (size_t)b*NG*ATOT + a;
                float best = g_cost[cb]; gs = 0;
                for (int g = 1; g < NG; g++) {
                    float c = g_cost[cb + (size_t)g*ATOT];
                    if (c < best) { best = c; gs = g; }
                }
            } else gs = __ffs(mask) - 1;        // argmax of one-hot = first (only) set bit
            float miou = g_iou[((size_t)b*NG + gs)*ATOT + a];
            int gx = hw % W, gy = hw / W;
            float tx = P[hw], ty = P[HW+hw], tw = P[2*HW+hw], th = P[3*HW+hw];
            float px = (tx + (float)gx)*s, py = (ty + (float)gy)*s;
            float pw = __expf(tw)*s, ph = __expf(th)*s;
            float bx = sl[gs*5+0], by = sl[gs*5+1], bw = sl[gs*5+2], bh = sl[gs*5+3];
            float iw = fmaxf(fminf(px + pw*0.5f, bx + bw*0.5f) - fmaxf(px - pw*0.5f, bx - bw*0.5f), 0.f);
            float ih = fmaxf(fminf(py + ph*0.5f, by + bh*0.5f) - fmaxf(py - ph*0.5f, by - bh*0.5f), 0.f);
            float it = iw*ih;
            float iou = it / (pw*ph + bw*bh - it + 1e-16f);
            aB = (double)(1.f - iou*iou);
            const float* Pc = P + 5*HW + hw;
            int tc = stc[gs];
            double sp = 0.0; float xt = 0.f;
            for (int c = 0; c < NC; c++) {
                float x = Pc[c*HW];
                sp += (double)(fmaxf(x, 0.f) + log1pf(expf(-fabsf(x))));   // softplus
                if (c == tc) xt = x;
            }
            aL = sp - (double)(xt * miou);      // bce(cls, onehot*miou) summed over classes
            aC -= (double)cf;                    // bce(conf,1) - bce(conf,0) = -conf
            aF = 1.0;
        }
    }
    int blk = b*gridDim.x + blockIdx.x;
    sred[tid] = aC; __syncthreads();
    for (int s2 = TPB/2; s2 > 0; s2 >>= 1) { if (tid < s2) sred[tid] += sred[tid+s2]; __syncthreads(); }
    if (tid == 0) g_pc[blk] = sred[0]; __syncthreads();
    sred[tid] = aB; __syncthreads();
    for (int s2 = TPB/2; s2 > 0; s2 >>= 1) { if (tid < s2) sred[tid] += sred[tid+s2]; __syncthreads(); }
    if (tid == 0) g_pb[blk] = sred[0]; __syncthreads();
    sred[tid] = aL; __syncthreads();
    for (int s2 = TPB/2; s2 > 0; s2 >>= 1) { if (tid < s2) sred[tid] += sred[tid+s2]; __syncthreads(); }
    if (tid == 0) g_pl[blk] = sred[0]; __syncthreads();
    sred[tid] = aF; __syncthreads();
    for (int s2 = TPB/2; s2 > 0; s2 >>= 1) { if (tid < s2) sred[tid] += sred[tid+s2]; __syncthreads(); }
    if (tid == 0) g_pf[blk] = sred[0];
}

// ---------------- kF: deterministic final reduction ----------------
__global__ __launch_bounds__(TPB) void kF(float* out) {
    __shared__ double sred[TPB];
    int tid = threadIdx.x;
    double c = 0.0, bb = 0.0, l = 0.0, f = 0.0;
    for (int i = tid; i < NPART; i += TPB) { c += g_pc[i]; bb += g_pb[i]; l += g_pl[i]; f += g_pf[i]; }
    sred[tid] = c;  __syncthreads();
    for (int s2 = TPB/2; s2 > 0; s2 >>= 1) { if (tid < s2) sred[tid] += sred[tid+s2]; __syncthreads(); }
    c = sred[0]; __syncthreads();
    sred[tid] = bb; __syncthreads();
    for (int s2 = TPB/2; s2 > 0; s2 >>= 1) { if (tid < s2) sred[tid] += sred[tid+s2]; __syncthreads(); }
    bb = sred[0]; __syncthreads();
    sred[tid] = l;  __syncthreads();
    for (int s2 = TPB/2; s2 > 0; s2 >>= 1) { if (tid < s2) sred[tid] += sred[tid+s2]; __syncthreads(); }
    l = sred[0]; __syncthreads();
    sred[tid] = f;  __syncthreads();
    for (int s2 = TPB/2; s2 > 0; s2 >>= 1) { if (tid < s2) sred[tid] += sred[tid+s2]; __syncthreads(); }
    f = sred[0];
    if (tid == 0) {
        double fg = f < 1.0 ? 1.0 : f;
        out[0] = (float)((5.0*bb + c + l) / fg);
    }
}

// ---------------- launch ----------------
extern "C" void kernel_launch(void* const* d_in, const int* in_sizes, int n_in,
                              void* d_out, int out_size) {
    (void)in_sizes; (void)n_in; (void)out_size;
    const float* p0  = (const float*)d_in[0];
    const float* p1  = (const float*)d_in[1];
    const float* p2  = (const float*)d_in[2];
    const float* lab = (const float*)d_in[3];
    kZ<<<(NB*ATOT + TPB - 1)/TPB, TPB>>>();
    dim3 gB(NBLKX, NB);
    kB<<<gB, TPB>>>(p0, p1, p2, lab);
    kC<<<NB*NG, TPB>>>();
    kD<<<gB, TPB>>>(p0, p1, p2, lab);
    kF<<<1, TPB>>>((float*)d_out);
}